// round 4
// baseline (speedup 1.0000x reference)
#include <cuda_runtime.h>

#define BATCH 128
#define CH 1024

// GEMM config
#define G_NTILE 64
#define G_KSPLIT 16
#define G_KCHUNK (CH / G_KSPLIT)   // 64
#define KT 32
#define SROW 34                    // row stride (floats): conflict-free LDS.64

// Scratch (allocation-free rule: __device__ globals)
static __device__ float g_h[BATCH * CH];     // 512 KB: h = visual + crossed
static __device__ float g_acc[BATCH * CH];   // 512 KB: GEMM accumulator (atomic)

typedef unsigned long long u64;
typedef unsigned int u32;

__device__ __forceinline__ float ex2f(float x) {
    float y;
    asm("ex2.approx.ftz.f32 %0, %1;" : "=f"(y) : "f"(x));
    return y;
}
__device__ __forceinline__ u64 pk(float lo, float hi) {
    u64 r; asm("mov.b64 %0, {%1,%2};" : "=l"(r) : "f"(lo), "f"(hi)); return r;
}
__device__ __forceinline__ u64 dup(float x) {
    u32 u = __float_as_uint(x);
    return ((u64)u << 32) | (u64)u;
}
__device__ __forceinline__ u64 mul2(u64 a, u64 b) {
    u64 r; asm("mul.rn.f32x2 %0, %1, %2;" : "=l"(r) : "l"(a), "l"(b)); return r;
}
__device__ __forceinline__ u64 add2(u64 a, u64 b) {
    u64 r; asm("add.rn.f32x2 %0, %1, %2;" : "=l"(r) : "l"(a), "l"(b)); return r;
}
__device__ __forceinline__ u64 fma2(u64 a, u64 b, u64 c) {
    u64 r; asm("fma.rn.f32x2 %0, %1, %2, %3;" : "=l"(r) : "l"(a), "l"(b), "l"(c)); return r;
}
__device__ __forceinline__ void upkf(float& lo, float& hi, u64 v) {
    asm("mov.b64 {%0,%1}, %2;" : "=f"(lo), "=f"(hi) : "l"(v));
}
__device__ __forceinline__ void upki(u32& lo, u32& hi, u64 v) {
    asm("mov.b64 {%0,%1}, %2;" : "=r"(lo), "=r"(hi) : "l"(v));
}
__device__ __forceinline__ u64 pki(u32 lo, u32 hi) {
    u64 r; asm("mov.b64 %0, {%1,%2};" : "=l"(r) : "r"(lo), "r"(hi)); return r;
}

// ---------------------------------------------------------------------------
// Kernel A: per-row softmax cross attention.
// crossed[b,i] = (sum_j e^{t_i v_j} v_j) / (sum_j e^{t_i v_j});  h = v_i + crossed
// v pre-scaled by log2(e) in smem; exp2 computed on BOTH pipes:
//   5/8 pairs via MUFU ex2, 3/8 pairs via FMA-pipe poly (packed f32x2).
// Also zeroes g_acc for the GEMM's atomic accumulation.
// ---------------------------------------------------------------------------
__global__ __launch_bounds__(256) void cross_kernel(
    const float* __restrict__ visual, const float* __restrict__ tactile)
{
    __shared__ __align__(16) float vl[CH];
    const int b = blockIdx.x >> 2;
    const int chunk = blockIdx.x & 3;
    const float LOG2E = 1.4426950408889634f;
    const float LN2   = 0.6931471805599453f;

    // zero the gemm accumulator (grid exactly covers BATCH*CH)
    g_acc[blockIdx.x * 256 + threadIdx.x] = 0.f;

    const float* vb = visual + b * CH;
#pragma unroll
    for (int k = 0; k < 4; k++) {
        int idx = threadIdx.x + k * 256;
        vl[idx] = vb[idx] * LOG2E;
    }
    __syncthreads();

    const int i = chunk * 256 + threadIdx.x;
    const float t = tactile[b * CH + i];
    const u64 tt = dup(t);

    // poly constants: 2^f, f in [-0.5, 0.5]  (Taylor of e^{f ln2})
    const u64 C0 = dup(1.0f);
    const u64 C1 = dup(0.69314718f);
    const u64 C2 = dup(0.24022651f);
    const u64 C3 = dup(0.05550411f);
    const u64 C4 = dup(0.00961813f);
    const u64 MAG2  = dup(12582912.0f);    // 1.5 * 2^23
    const u64 NMAG2 = dup(-12582912.0f);
    const u64 NONE2 = dup(-1.0f);

    u64 sumM = 0ull, dotM = 0ull, sumP = 0ull, dotP = 0ull;

    const u64* vl2 = reinterpret_cast<const u64*>(vl);

#pragma unroll 2
    for (int jj = 0; jj < CH / 16; jj++) {
        const u64* p = vl2 + jj * 8;
        // MUFU path: pairs 0..4
#pragma unroll
        for (int q = 0; q < 5; q++) {
            u64 vv = p[q];
            u64 m = mul2(tt, vv);
            float ml, mh; upkf(ml, mh, m);
            u64 ee = pk(ex2f(ml), ex2f(mh));
            sumM = add2(sumM, ee);
            dotM = fma2(ee, vv, dotM);
        }
        // FMA-pipe poly path: pairs 5..7
#pragma unroll
        for (int q = 5; q < 8; q++) {
            u64 vv = p[q];
            u64 m = mul2(tt, vv);
            u64 z = add2(m, MAG2);            // round-to-nearest via magic
            u64 r = add2(z, NMAG2);           // r = round(m)
            u64 f = fma2(r, NONE2, m);        // f = m - r, in [-0.5, 0.5]
            u64 pp = fma2(C4, f, C3);
            pp = fma2(pp, f, C2);
            pp = fma2(pp, f, C1);
            pp = fma2(pp, f, C0);
            // exponent injection: bits(z) = 0x4B400000 + n  ->  (z<<23) = n<<23
            u32 zl, zh, pl, ph;
            upki(zl, zh, z);
            upki(pl, ph, pp);
            u32 el = pl + (zl << 23);
            u32 eh = ph + (zh << 23);
            u64 ee = pki(el, eh);
            sumP = add2(sumP, ee);
            dotP = fma2(ee, vv, dotP);
        }
    }

    float s0, s1, s2, s3, d0, d1, d2, d3;
    upkf(s0, s1, sumM); upkf(s2, s3, sumP);
    upkf(d0, d1, dotM); upkf(d2, d3, dotP);
    float sum = (s0 + s1) + (s2 + s3);
    float dot = (d0 + d1) + (d2 + d3);              // = log2e * sum e_j v_j
    float h = (vl[i] + __fdividef(dot, sum)) * LN2; // vl[i]*ln2 = v_i
    g_h[b * CH + i] = h;
}

// ---------------------------------------------------------------------------
// Kernel B: split-K GEMM with k-packed f32x2 FFMA.
// y[b,o] += sum_{k in chunk} Wc[o,k] * h[b,k];  Wc = center tap of 3x3 conv.
// 128 threads, 8b x 8o per thread (acc packed over k-pairs), CTA tile 128b x 64o.
// grid = 16 n-tiles x 16 k-splits. Results via atomicAdd into g_acc.
// ---------------------------------------------------------------------------
__global__ __launch_bounds__(128) void gemm_kernel(const float* __restrict__ conv_w)
{
    __shared__ __align__(16) float sh[BATCH][SROW];    // 128 x 34 floats
    __shared__ __align__(16) float sw[G_NTILE][SROW];  // 64 x 34 floats

    const int nb = blockIdx.x & 15;
    const int kz = blockIdx.x >> 4;
    const int nbase = nb * G_NTILE;
    const int kbase = kz * G_KCHUNK;

    const int tx = threadIdx.x & 7;    // o lane (8 groups of 8)
    const int ty = threadIdx.x >> 3;   // b lane (16 groups of 8)

    u64 acc[8][8] = {};

    for (int kk = 0; kk < G_KCHUNK; kk += KT) {
        if (kk) __syncthreads();
        // stage h: 128 x 32 floats (coalesced float4)
#pragma unroll
        for (int it = 0; it < 8; it++) {
            int l = threadIdx.x + it * 128;
            int r = l >> 3, c = (l & 7) * 4;
            float4 hv = *(const float4*)&g_h[r * CH + kbase + kk + c];
            sh[r][c] = hv.x; sh[r][c + 1] = hv.y; sh[r][c + 2] = hv.z; sh[r][c + 3] = hv.w;
        }
        // stage w: 64 x 32 center taps (stride-9 gather)
#pragma unroll
        for (int it = 0; it < 16; it++) {
            int l = threadIdx.x + it * 128;
            int o = l >> 5, c = l & 31;
            sw[o][c] = conv_w[((nbase + o) * CH + (kbase + kk + c)) * 9 + 4];
        }
        __syncthreads();

#pragma unroll
        for (int kp = 0; kp < KT / 2; kp++) {
            u64 hb[8], wo[8];
#pragma unroll
            for (int bi = 0; bi < 8; bi++)
                hb[bi] = *(const u64*)&sh[ty + 16 * bi][kp * 2];
#pragma unroll
            for (int oi = 0; oi < 8; oi++)
                wo[oi] = *(const u64*)&sw[tx + 8 * oi][kp * 2];
#pragma unroll
            for (int bi = 0; bi < 8; bi++)
#pragma unroll
                for (int oi = 0; oi < 8; oi++)
                    acc[bi][oi] = fma2(hb[bi], wo[oi], acc[bi][oi]);
        }
    }

    // epilogue: fold k-pair halves, atomic accumulate
#pragma unroll
    for (int bi = 0; bi < 8; bi++) {
        int b = ty + 16 * bi;
#pragma unroll
        for (int oi = 0; oi < 8; oi++) {
            float lo, hi; upkf(lo, hi, acc[bi][oi]);
            atomicAdd(&g_acc[b * CH + nbase + tx + 8 * oi], lo + hi);
        }
    }
}

// ---------------------------------------------------------------------------
// Kernel C: conv bias + BN (eval) + LeakyReLU(0.1)
// ---------------------------------------------------------------------------
__global__ __launch_bounds__(256) void final_kernel(
    const float* __restrict__ cb, const float* __restrict__ gamma,
    const float* __restrict__ beta, const float* __restrict__ mean,
    const float* __restrict__ var, float* __restrict__ out)
{
    const int idx = blockIdx.x * 256 + threadIdx.x;
    const int o = idx & (CH - 1);
    float s = g_acc[idx];
    float A = gamma[o] * rsqrtf(var[o] + 1e-5f);
    float v = (s + cb[o] - mean[o]) * A + beta[o];
    out[idx] = v > 0.f ? v : 0.1f * v;
}

extern "C" void kernel_launch(void* const* d_in, const int* in_sizes, int n_in,
                              void* d_out, int out_size)
{
    const float* visual  = (const float*)d_in[0];
    const float* tactile = (const float*)d_in[1];
    const float* conv_w  = (const float*)d_in[2];
    const float* conv_b  = (const float*)d_in[3];
    const float* gamma   = (const float*)d_in[4];
    const float* beta    = (const float*)d_in[5];
    const float* mean    = (const float*)d_in[6];
    const float* var     = (const float*)d_in[7];
    float* out = (float*)d_out;

    cross_kernel<<<BATCH * 4, 256>>>(visual, tactile);
    gemm_kernel<<<(CH / G_NTILE) * G_KSPLIT, 128>>>(conv_w);
    final_kernel<<<(BATCH * CH) / 256, 256>>>(conv_b, gamma, beta, mean, var, out);
}

// round 5
// speedup vs baseline: 1.8406x; 1.8406x over previous
#include <cuda_runtime.h>

#define BATCH 128
#define CH 1024

// Table config
#define G 128
#define GRANGE 6.0f
#define GSTEP (2.0f * GRANGE / (G - 1))

// GEMM config
#define G_NTILE 64
#define G_KSPLIT 16
#define G_KCHUNK (CH / G_KSPLIT)   // 64
#define KT 32
#define SROW 34                    // row stride (floats): conflict-free LDS.64

// Scratch (allocation-free rule: __device__ globals)
static __device__ float g_h[BATCH * CH];     // 512 KB: h = visual + crossed
static __device__ float g_acc[BATCH * CH];   // 512 KB: GEMM accumulator (atomic)
static __device__ float g_tab[BATCH][G];     // 64 KB: crossed value table
static __device__ float g_der[BATCH][G];     // 64 KB: d(crossed)/du (u = grid coord)

typedef unsigned long long u64;
typedef unsigned int u32;

__device__ __forceinline__ float ex2f(float x) {
    float y;
    asm("ex2.approx.ftz.f32 %0, %1;" : "=f"(y) : "f"(x));
    return y;
}
__device__ __forceinline__ u64 fma2(u64 a, u64 b, u64 c) {
    u64 r; asm("fma.rn.f32x2 %0, %1, %2, %3;" : "=l"(r) : "l"(a), "l"(b), "l"(c)); return r;
}
__device__ __forceinline__ void upkf(float& lo, float& hi, u64 v) {
    asm("mov.b64 {%0,%1}, %2;" : "=f"(lo), "=f"(hi) : "l"(v));
}

// ---------------------------------------------------------------------------
// Kernel A1: build per-batch tables of g(s) = sum_j e^{s v_j} v_j / sum_j e^{s v_j}
// and its derivative g'(s) = M2/D - g^2, on G grid points over [-GRANGE,GRANGE].
// grid = BATCH blocks x G threads (one grid point per thread).
// v pre-scaled by log2(e); e = ex2(s * vl_j). Per element: 1 MUFU + 4 fma ops.
// ---------------------------------------------------------------------------
__global__ __launch_bounds__(G) void table_kernel(const float* __restrict__ visual)
{
    __shared__ __align__(16) float vl[CH];    // v * log2e
    __shared__ __align__(16) float vl2[CH];   // (v * log2e)^2
    const int b = blockIdx.x;
    const float LOG2E = 1.4426950408889634f;
    const float LN2   = 0.6931471805599453f;

    const float* vb = visual + b * CH;
#pragma unroll
    for (int k = 0; k < CH / G; k++) {
        int idx = threadIdx.x + k * G;
        float v = vb[idx] * LOG2E;
        vl[idx] = v;
        vl2[idx] = v * v;
    }
    __syncthreads();

    const float s = -GRANGE + GSTEP * (float)threadIdx.x;

    float den0 = 0.f, den1 = 0.f;
    float num0 = 0.f, num1 = 0.f;
    float m20 = 0.f, m21 = 0.f;
    const float4* v4 = reinterpret_cast<const float4*>(vl);
    const float4* w4 = reinterpret_cast<const float4*>(vl2);
#pragma unroll 4
    for (int j = 0; j < CH / 4; j++) {
        float4 v = v4[j];
        float4 w = w4[j];
        float e0 = ex2f(s * v.x);
        float e1 = ex2f(s * v.y);
        float e2 = ex2f(s * v.z);
        float e3 = ex2f(s * v.w);
        den0 += e0 + e2;
        den1 += e1 + e3;
        num0 = fmaf(e0, v.x, num0);
        num1 = fmaf(e1, v.y, num1);
        num0 = fmaf(e2, v.z, num0);
        num1 = fmaf(e3, v.w, num1);
        m20 = fmaf(e0, w.x, m20);
        m21 = fmaf(e1, w.y, m21);
        m20 = fmaf(e2, w.z, m20);
        m21 = fmaf(e3, w.w, m21);
    }
    float den = den0 + den1;
    float num = num0 + num1;
    float m2  = m20 + m21;

    float inv = __fdividef(1.0f, den);
    float nd = num * inv;                          // = log2e * g
    float gval = nd * LN2;                         // crossed value
    float gp = (LN2 * LN2) * (m2 * inv - nd * nd); // dg/ds
    g_tab[b][threadIdx.x] = gval;
    g_der[b][threadIdx.x] = gp * GSTEP;            // derivative in grid-coord units
}

// ---------------------------------------------------------------------------
// Kernel A2: cubic Hermite interpolation -> h = visual + g(t). Zeroes g_acc.
// grid = BATCH*4 blocks x 256 threads (one (b,i) per thread).
// ---------------------------------------------------------------------------
__global__ __launch_bounds__(256) void interp_kernel(
    const float* __restrict__ visual, const float* __restrict__ tactile)
{
    __shared__ float tab[G];
    __shared__ float der[G];
    const int b = blockIdx.x >> 2;
    const int q = blockIdx.x & 3;

    if (threadIdx.x < G) tab[threadIdx.x] = g_tab[b][threadIdx.x];
    else                 der[threadIdx.x - G] = g_der[b][threadIdx.x - G];

    // zero the gemm accumulator (grid exactly covers BATCH*CH)
    g_acc[blockIdx.x * 256 + threadIdx.x] = 0.f;
    __syncthreads();

    const int i = q * 256 + threadIdx.x;
    const float t = tactile[b * CH + i];

    float x = (t + GRANGE) * (1.0f / GSTEP);            // grid coordinate
    x = fminf(fmaxf(x, 0.0f), (float)(G - 1) - 1e-3f);  // safety clamp
    int i1 = (int)x;
    float u = x - (float)i1;
    float p1 = tab[i1], p2 = tab[i1 + 1];
    float m1 = der[i1], m2 = der[i1 + 1];

    // cubic Hermite
    float c2 = 3.0f * (p2 - p1) - 2.0f * m1 - m2;
    float c3 = 2.0f * (p1 - p2) + m1 + m2;
    float crossed = ((c3 * u + c2) * u + m1) * u + p1;

    g_h[b * CH + i] = visual[b * CH + i] + crossed;
}

// ---------------------------------------------------------------------------
// Kernel B: split-K GEMM with k-packed f32x2 FFMA.
// y[b,o] += sum_{k in chunk} Wc[o,k] * h[b,k];  Wc = center tap of 3x3 conv.
// 128 threads, 8b x 8o per thread (acc packed over k-pairs), CTA tile 128b x 64o.
// grid = 16 n-tiles x 16 k-splits. Results via atomicAdd into g_acc.
// ---------------------------------------------------------------------------
__global__ __launch_bounds__(128) void gemm_kernel(const float* __restrict__ conv_w)
{
    __shared__ __align__(16) float sh[BATCH][SROW];    // 128 x 34 floats
    __shared__ __align__(16) float sw[G_NTILE][SROW];  // 64 x 34 floats

    const int nb = blockIdx.x & 15;
    const int kz = blockIdx.x >> 4;
    const int nbase = nb * G_NTILE;
    const int kbase = kz * G_KCHUNK;

    const int tx = threadIdx.x & 7;    // o lane (8 groups of 8)
    const int ty = threadIdx.x >> 3;   // b lane (16 groups of 8)

    u64 acc[8][8] = {};

    for (int kk = 0; kk < G_KCHUNK; kk += KT) {
        if (kk) __syncthreads();
        // stage h: 128 x 32 floats (coalesced float4)
#pragma unroll
        for (int it = 0; it < 8; it++) {
            int l = threadIdx.x + it * 128;
            int r = l >> 3, c = (l & 7) * 4;
            float4 hv = *(const float4*)&g_h[r * CH + kbase + kk + c];
            sh[r][c] = hv.x; sh[r][c + 1] = hv.y; sh[r][c + 2] = hv.z; sh[r][c + 3] = hv.w;
        }
        // stage w: 64 x 32 center taps (stride-9 gather)
#pragma unroll
        for (int it = 0; it < 16; it++) {
            int l = threadIdx.x + it * 128;
            int o = l >> 5, c = l & 31;
            sw[o][c] = conv_w[((nbase + o) * CH + (kbase + kk + c)) * 9 + 4];
        }
        __syncthreads();

#pragma unroll
        for (int kp = 0; kp < KT / 2; kp++) {
            u64 hb[8], wo[8];
#pragma unroll
            for (int bi = 0; bi < 8; bi++)
                hb[bi] = *(const u64*)&sh[ty + 16 * bi][kp * 2];
#pragma unroll
            for (int oi = 0; oi < 8; oi++)
                wo[oi] = *(const u64*)&sw[tx + 8 * oi][kp * 2];
#pragma unroll
            for (int bi = 0; bi < 8; bi++)
#pragma unroll
                for (int oi = 0; oi < 8; oi++)
                    acc[bi][oi] = fma2(hb[bi], wo[oi], acc[bi][oi]);
        }
    }

    // epilogue: fold k-pair halves, atomic accumulate
#pragma unroll
    for (int bi = 0; bi < 8; bi++) {
        int b = ty + 16 * bi;
#pragma unroll
        for (int oi = 0; oi < 8; oi++) {
            float lo, hi; upkf(lo, hi, acc[bi][oi]);
            atomicAdd(&g_acc[b * CH + nbase + tx + 8 * oi], lo + hi);
        }
    }
}

// ---------------------------------------------------------------------------
// Kernel C: conv bias + BN (eval) + LeakyReLU(0.1)
// ---------------------------------------------------------------------------
__global__ __launch_bounds__(256) void final_kernel(
    const float* __restrict__ cb, const float* __restrict__ gamma,
    const float* __restrict__ beta, const float* __restrict__ mean,
    const float* __restrict__ var, float* __restrict__ out)
{
    const int idx = blockIdx.x * 256 + threadIdx.x;
    const int o = idx & (CH - 1);
    float s = g_acc[idx];
    float A = gamma[o] * rsqrtf(var[o] + 1e-5f);
    float v = (s + cb[o] - mean[o]) * A + beta[o];
    out[idx] = v > 0.f ? v : 0.1f * v;
}

extern "C" void kernel_launch(void* const* d_in, const int* in_sizes, int n_in,
                              void* d_out, int out_size)
{
    const float* visual  = (const float*)d_in[0];
    const float* tactile = (const float*)d_in[1];
    const float* conv_w  = (const float*)d_in[2];
    const float* conv_b  = (const float*)d_in[3];
    const float* gamma   = (const float*)d_in[4];
    const float* beta    = (const float*)d_in[5];
    const float* mean    = (const float*)d_in[6];
    const float* var     = (const float*)d_in[7];
    float* out = (float*)d_out;

    table_kernel<<<BATCH, G>>>(visual);
    interp_kernel<<<BATCH * 4, 256>>>(visual, tactile);
    gemm_kernel<<<(CH / G_NTILE) * G_KSPLIT, 128>>>(conv_w);
    final_kernel<<<(BATCH * CH) / 256, 256>>>(conv_b, gamma, beta, mean, var, out);
}